// round 13
// baseline (speedup 1.0000x reference)
#include <cuda_runtime.h>
#include <cuda_bf16.h>
#include <math.h>

#define NMAX  50176
#define EMAX  1664000
#define GMAX  64
#define FDIM  128
#define HDIM  128
#define KDIM  32

typedef unsigned long long ull;

// ---------------- scratch (static device globals; no allocation) -------------
// INVARIANT at kernel_launch entry: g_cnt_i, g_msum1, g_msum2, g_tick1, g_tick2
// are zero (zero-init at load; re-zeroed each launch at the tail / last block).
__device__ float g_dinv[NMAX];
__device__ uint2 g_y1b [NMAX * 32];     // bf16(xw = X@W1), 256B/row
__device__ uint2 g_hb  [NMAX * 32];     // bf16(h), 256B/row
__device__ float g_y2  [NMAX * KDIM];   // fp32 y2 (self-loop term)
__device__ unsigned short g_y2b[NMAX * KDIM];  // bf16 copy of y2
__device__ float g_z   [NMAX * KDIM];
__device__ float g_msum1[GMAX * HDIM];
__device__ float g_r1  [GMAX * HDIM];
__device__ float g_msum2[GMAX * KDIM];
__device__ float g_r2  [GMAX * KDIM];
__device__ float g_cnt [GMAX];
__device__ int   g_cnt_i[NMAX];
__device__ int   g_rowstart[NMAX];
__device__ int   g_cursor[NMAX];
__device__ int   g_bsums[64];
__device__ int   g_csr  [EMAX];
__device__ int   g_is64_batch;
__device__ unsigned g_tick1;
__device__ unsigned g_tick2;

__device__ __forceinline__ long long ld_idx(const void* p, long long pos, int is64) {
    if (is64) return ((const long long*)p)[pos];
    return (long long)((const int*)p)[pos];
}

__device__ __forceinline__ void fma2(ull& d, ull a, ull b) {
    asm("fma.rn.f32x2 %0, %1, %2, %0;" : "+l"(d) : "l"(a), "l"(b));
}
__device__ __forceinline__ ull pack2(float x, float y) {
    ull r; asm("mov.b64 %0, {%1, %2};" : "=l"(r) : "f"(x), "f"(y)); return r;
}
__device__ __forceinline__ void unpack2(ull v, float& x, float& y) {
    asm("mov.b64 {%0, %1}, %2;" : "=f"(x), "=f"(y) : "l"(v));
}
__device__ __forceinline__ uint2 pack_bf16x4(float a, float b, float c, float d) {
    __nv_bfloat162 lo = __floats2bfloat162_rn(a, b);
    __nv_bfloat162 hi = __floats2bfloat162_rn(c, d);
    uint2 o;
    o.x = *(unsigned*)&lo;
    o.y = *(unsigned*)&hi;
    return o;
}
__device__ __forceinline__ void unpack_bf16x4(uint2 v, float4& o) {
    float2 a = __bfloat1622float2(*(__nv_bfloat162*)&v.x);
    float2 b = __bfloat1622float2(*(__nv_bfloat162*)&v.y);
    o.x = a.x; o.y = a.y; o.z = b.x; o.w = b.y;
}

// In-block ei dtype detection: warp 0 samples 64 words, ballots, broadcasts.
__device__ __forceinline__ int detect_ei_block(const void* ei, long long E, int N,
                                               int* s_flag) {
    int t = threadIdx.x;
    if (t < 32) {
        const ull* p = (const ull*)ei;
        bool ok = true;
#pragma unroll
        for (int u = 0; u < 2; u++) {
            int i = t * 2 + u;
            long long w = (long long)i * (E - 1) / 63;
            if (p[w] >= (ull)N) ok = false;
        }
        unsigned all1 = __all_sync(0xffffffffu, ok);
        if (t == 0) *s_flag = (int)(all1 != 0);
    }
    __syncthreads();
    return *s_flag;
}

// side-stream: batch dtype (consumed by cnt/agg1/gemm2/agg2/softmax)
__global__ void detect_batch_kernel(const void* batch, int N) {
    int lane = threadIdx.x;
    const ull* q = (const ull*)batch;
    bool ok2 = true;
#pragma unroll
    for (int u = 0; u < 2; u++) {
        int i = lane * 2 + u;
        long long w = (long long)(N / 2) - 1 - i;
        if (w >= 0 && q[w] >= (ull)GMAX) ok2 = false;
    }
    unsigned all2 = __all_sync(0xffffffffu, ok2);
    if (lane == 0) g_is64_batch = (int)(all2 != 0);
}

// ------- per-graph node counts via binary search over sorted batch -----------
__global__ void cnt_kernel(const void* __restrict__ batch, int N) {
    int g = threadIdx.x;
    if (g > GMAX) return;
    __shared__ int start[GMAX + 1];
    int is64 = g_is64_batch;
    int lo = 0, hi = N;
    while (lo < hi) {
        int mid = (lo + hi) >> 1;
        int v = (int)ld_idx(batch, mid, is64);
        if (v < g) lo = mid + 1; else hi = mid;
    }
    start[g] = lo;
    __syncthreads();
    if (g < GMAX) g_cnt[g] = (float)(start[g + 1] - start[g]);
}

// ------------- degree histogram, 8 edges/thread; inline dtype detect ---------
__global__ void hist_kernel(const void* __restrict__ ei, long long E, int N) {
    __shared__ int s_flag;
    int is64 = detect_ei_block(ei, E, N, &s_flag);
    long long base = ((long long)blockIdx.x * blockDim.x + threadIdx.x) * 8;
    int d[8]; bool v[8];
#pragma unroll
    for (int u = 0; u < 8; u++) {
        long long e = base + u;
        v[u] = e < E;
        d[u] = v[u] ? (int)ld_idx(ei, E + e, is64) : 0;
    }
#pragma unroll
    for (int u = 0; u < 8; u++)
        if (v[u]) atomicAdd(&g_cnt_i[d[u]], 1);
}

// ------------- prefix-sum over node counts (2 kernels) ------------------------
__global__ void scan1_kernel(int N) {
    __shared__ int sm[1024];
    int t = threadIdx.x;
    int idx = blockIdx.x * 1024 + t;
    int val = (idx < N) ? g_cnt_i[idx] : 0;
    sm[t] = val;
    __syncthreads();
    for (int off = 1; off < 1024; off <<= 1) {
        int x = (t >= off) ? sm[t - off] : 0;
        __syncthreads();
        sm[t] += x;
        __syncthreads();
    }
    if (idx < N) g_rowstart[idx] = sm[t] - val;   // exclusive, block-local
    if (t == 1023) g_bsums[blockIdx.x] = sm[1023];
}
__global__ void scan3_kernel(int N, int nb) {
    __shared__ int pref[64];
    int t = threadIdx.x;
    if (t < 32) {
        int a = (t < nb) ? g_bsums[t] : 0;
        int b = (t + 32 < nb) ? g_bsums[t + 32] : 0;
        int sa = a, sb = b;
#pragma unroll
        for (int o = 1; o < 32; o <<= 1) {
            int va = __shfl_up_sync(0xffffffffu, sa, o);
            int vb = __shfl_up_sync(0xffffffffu, sb, o);
            if (t >= o) { sa += va; sb += vb; }
        }
        int totalA = __shfl_sync(0xffffffffu, sa, 31);
        pref[t]      = sa - a;
        pref[t + 32] = totalA + sb - b;
    }
    __syncthreads();
    int idx = blockIdx.x * blockDim.x + t;
    if (idx >= N) return;
    int v = g_rowstart[idx] + pref[idx >> 10];
    g_rowstart[idx] = v;
    g_cursor[idx]   = v;
    g_dinv[idx]     = rsqrtf((float)g_cnt_i[idx] + 1.0f);   // +1 self loop
}

// ------------- scatter-fill CSR, 8 edges/thread; inline dtype detect ----------
__global__ void fill_kernel(const void* __restrict__ ei, long long E, int N) {
    __shared__ int s_flag;
    int is64 = detect_ei_block(ei, E, N, &s_flag);
    long long base = ((long long)blockIdx.x * blockDim.x + threadIdx.x) * 8;
    int s[8], d[8]; bool v[8];
#pragma unroll
    for (int u = 0; u < 8; u++) {
        long long e = base + u;
        v[u] = e < E;
        s[u] = v[u] ? (int)ld_idx(ei, e, is64) : 0;
        d[u] = v[u] ? (int)ld_idx(ei, E + e, is64) : 0;
    }
#pragma unroll
    for (int u = 0; u < 8; u++) {
        if (v[u]) {
            int pos = atomicAdd(&g_cursor[d[u]], 1);
            g_csr[pos] = s[u];
        }
    }
}

// ------- GEMM1 (f32x2 FMAs): y1b = bf16(X @ W1)  (bf16-only output) ----------
__global__ void __launch_bounds__(128) gemm1_kernel(
    const float* __restrict__ X, const float* __restrict__ W, int N)
{
    __shared__ float As[16][64];
    __shared__ float Bs[16][128];
    int t  = threadIdx.x;
    int tx = t & 15;
    int ty = t >> 4;
    int rowBase = blockIdx.x * 64;

    ull acc2[8][4];
#pragma unroll
    for (int i = 0; i < 8; i++)
#pragma unroll
        for (int j = 0; j < 4; j++) acc2[i][j] = 0ULL;

    for (int k0 = 0; k0 < 128; k0 += 16) {
#pragma unroll
        for (int u = 0; u < 2; u++) {
            int idx = t * 8 + u * 4;
            int r = idx >> 4, c = idx & 15;
            int grow = rowBase + r;
            float4 v = make_float4(0.f, 0.f, 0.f, 0.f);
            if (grow < N) v = *(const float4*)(X + (size_t)grow * 128 + k0 + c);
            As[c + 0][r] = v.x; As[c + 1][r] = v.y;
            As[c + 2][r] = v.z; As[c + 3][r] = v.w;
        }
#pragma unroll
        for (int u = 0; u < 4; u++) {
            int idx = t * 16 + u * 4;
            int r = idx >> 7, c = idx & 127;
            *(float4*)&Bs[r][c] = *(const float4*)(W + (k0 + r) * 128 + c);
        }
        __syncthreads();
#pragma unroll
        for (int kk = 0; kk < 16; kk++) {
            float a[8];
            ull b2[4];
            *(float4*)&a[0] = *(float4*)&As[kk][ty * 8];
            *(float4*)&a[4] = *(float4*)&As[kk][ty * 8 + 4];
            *(ulonglong2*)&b2[0] = *(ulonglong2*)&Bs[kk][tx * 8];
            *(ulonglong2*)&b2[2] = *(ulonglong2*)&Bs[kk][tx * 8 + 4];
#pragma unroll
            for (int i = 0; i < 8; i++) {
                ull a2 = pack2(a[i], a[i]);
#pragma unroll
                for (int j = 0; j < 4; j++) fma2(acc2[i][j], a2, b2[j]);
            }
        }
        __syncthreads();
    }
#pragma unroll
    for (int i = 0; i < 8; i++) {
        int grow = rowBase + ty * 8 + i;
        if (grow < N) {
#pragma unroll
            for (int j2 = 0; j2 < 2; j2++) {
                float4 v;
                unpack2(acc2[i][j2 * 2 + 0], v.x, v.y);
                unpack2(acc2[i][j2 * 2 + 1], v.z, v.w);
                g_y1b[(size_t)grow * 32 + tx * 2 + j2] = pack_bf16x4(v.x, v.y, v.z, v.w);
            }
        }
    }
}

// ---- agg1: h = elu(dinv[i]*(dinv[i]*xw[i] + sum dinv[s]*xw[s]) + b1) --------
// Block-level pool reduction + LAST BLOCK computes master1 (r1) inline.
__global__ void __launch_bounds__(256) agg1_kernel(
    const float* __restrict__ b1, const void* __restrict__ batch,
    const float* __restrict__ mW1, const float* __restrict__ mb1, int N)
{
    __shared__ float4 hs[8][32];
    __shared__ int s_g0;
    __shared__ unsigned s_rank;
    int t = threadIdx.x;
    int wid = t >> 5;
    int lane = t & 31;
    int i = blockIdx.x * 8 + wid;      // node index
    int is64 = g_is64_batch;
    if (t == 0) {
        int n0 = blockIdx.x * 8;
        s_g0 = (n0 < N) ? (int)ld_idx(batch, n0, is64) : 0;
    }
    __syncthreads();
    int g0 = s_g0;

    float4 h = make_float4(0.f, 0.f, 0.f, 0.f);
    int g = g0;
    bool active = (i < N);
    if (active) {
        int beg  = g_rowstart[i];
        int cntE = g_cnt_i[i];
        float dv = g_dinv[i];
        float4 self;
        unpack_bf16x4(g_y1b[(size_t)i * 32 + lane], self);
        float4 acc;
        acc.x = dv * self.x; acc.y = dv * self.y;
        acc.z = dv * self.z; acc.w = dv * self.w;
        int full = cntE & ~31;
        for (int k = 0; k < full; k += 32) {
            int   myS = g_csr[beg + k + lane];
            float myD = g_dinv[myS];
#pragma unroll 16
            for (int j = 0; j < 32; j++) {
                int   s = __shfl_sync(0xffffffffu, myS, j);
                float w = __shfl_sync(0xffffffffu, myD, j);
                float4 v;
                unpack_bf16x4(g_y1b[(size_t)s * 32 + lane], v);
                acc.x += w * v.x; acc.y += w * v.y;
                acc.z += w * v.z; acc.w += w * v.w;
            }
        }
        int rem = cntE - full;
        if (rem) {
            int   myS = (lane < rem) ? g_csr[beg + full + lane] : 0;
            float myD = (lane < rem) ? g_dinv[myS] : 0.f;
            for (int j = 0; j < rem; j++) {
                int   s = __shfl_sync(0xffffffffu, myS, j);
                float w = __shfl_sync(0xffffffffu, myD, j);
                float4 v;
                unpack_bf16x4(g_y1b[(size_t)s * 32 + lane], v);
                acc.x += w * v.x; acc.y += w * v.y;
                acc.z += w * v.z; acc.w += w * v.w;
            }
        }
        float4 bb = ((const float4*)b1)[lane];
        float vx = dv * acc.x + bb.x; h.x = vx > 0.f ? vx : expm1f(vx);
        float vy = dv * acc.y + bb.y; h.y = vy > 0.f ? vy : expm1f(vy);
        float vz = dv * acc.z + bb.z; h.z = vz > 0.f ? vz : expm1f(vz);
        float vw = dv * acc.w + bb.w; h.w = vw > 0.f ? vw : expm1f(vw);
        g_hb[(size_t)i * 32 + lane] = pack_bf16x4(h.x, h.y, h.z, h.w);
        g = (int)ld_idx(batch, i, is64);
    }
    bool inblk = active && (g == g0);
    hs[wid][lane] = inblk ? h : make_float4(0.f, 0.f, 0.f, 0.f);
    if (active && !inblk) {
        float* ms = g_msum1 + g * HDIM + lane * 4;
        asm volatile("red.global.add.v4.f32 [%0], {%1, %2, %3, %4};"
                     :: "l"(ms), "f"(h.x), "f"(h.y), "f"(h.z), "f"(h.w) : "memory");
    }
    __syncthreads();
    if (wid == 0) {
        float4 a = hs[0][lane];
#pragma unroll
        for (int w2 = 1; w2 < 8; w2++) {
            float4 b = hs[w2][lane];
            a.x += b.x; a.y += b.y; a.z += b.z; a.w += b.w;
        }
        float* ms = g_msum1 + g0 * HDIM + lane * 4;
        asm volatile("red.global.add.v4.f32 [%0], {%1, %2, %3, %4};"
                     :: "l"(ms), "f"(a.x), "f"(a.y), "f"(a.z), "f"(a.w) : "memory");
    }
    // ---- grid-tail: last block computes master1 ----
    __threadfence();
    __syncthreads();
    if (t == 0) s_rank = atomicAdd(&g_tick1, 1);
    __syncthreads();
    if (s_rank == gridDim.x - 1) {
        __threadfence();
        if (t == 0) g_tick1 = 0;     // reset for next replay
        int j = t & 127;             // output column
        int half = t >> 7;           // 0..1 -> graph halves
        for (int gb = half * 32; gb < half * 32 + 32; gb += 4) {
            float inv[4], acc[4];
#pragma unroll
            for (int u = 0; u < 4; u++) {
                inv[u] = 1.f / fmaxf(g_cnt[gb + u], 1.f);
                acc[u] = mb1[j];
            }
            for (int k = 0; k < HDIM; k++) {
                float w = mW1[k * HDIM + j];
#pragma unroll
                for (int u = 0; u < 4; u++)
                    acc[u] += (g_msum1[(gb + u) * HDIM + k] * inv[u]) * w;
            }
#pragma unroll
            for (int u = 0; u < 4; u++)
                g_r1[(gb + u) * HDIM + j] = fmaxf(acc[u], 0.f);
        }
    }
}

// --- GEMM2 (f32x2): y2 = dinv.*((bf16 h + r1[batch]) @ W2); bf16 copy y2b ----
__global__ void __launch_bounds__(128) gemm2_kernel(
    const void* __restrict__ batch, const float* __restrict__ W2, int N)
{
    __shared__ float Ws[128 * 32];
    int t = threadIdx.x;
#pragma unroll
    for (int u = 0; u < 8; u++) {
        int idx = u * 512 + t * 4;
        *(float4*)&Ws[idx] = *(const float4*)&W2[idx];
    }
    __syncthreads();
    int i = blockIdx.x * 128 + t;
    if (i >= N) return;
    int g = (int)ld_idx(batch, i, g_is64_batch);
    const uint2* hr = g_hb + (size_t)i * 32;
    const float* rr = g_r1 + g * 128;
    ull acc2[16];
#pragma unroll
    for (int j = 0; j < 16; j++) acc2[j] = 0ULL;
#pragma unroll 2
    for (int k0 = 0; k0 < 128; k0 += 4) {
        float4 xv;
        unpack_bf16x4(hr[k0 >> 2], xv);
        float4 rv = *(const float4*)(rr + k0);
        float xs[4] = {xv.x + rv.x, xv.y + rv.y, xv.z + rv.z, xv.w + rv.w};
#pragma unroll
        for (int kk = 0; kk < 4; kk++) {
            const ull* wrow = (const ull*)&Ws[(k0 + kk) * 32];
            ull x2 = pack2(xs[kk], xs[kk]);
#pragma unroll
            for (int j = 0; j < 16; j++) fma2(acc2[j], x2, wrow[j]);
        }
    }
    float dv = g_dinv[i];
#pragma unroll
    for (int j4 = 0; j4 < 8; j4++) {
        float4 v;
        unpack2(acc2[j4 * 2 + 0], v.x, v.y);
        unpack2(acc2[j4 * 2 + 1], v.z, v.w);
        v.x *= dv; v.y *= dv; v.z *= dv; v.w *= dv;
        *(float4*)(g_y2 + (size_t)i * 32 + j4 * 4) = v;
        __nv_bfloat162 lo = __floats2bfloat162_rn(v.x, v.y);
        __nv_bfloat162 hi = __floats2bfloat162_rn(v.z, v.w);
        unsigned* dstb = (unsigned*)(g_y2b + (size_t)i * 32 + j4 * 4);
        dstb[0] = *(unsigned*)&lo;
        dstb[1] = *(unsigned*)&hi;
    }
}

// ----- agg2: Z = dinv*(self + sum) + b2; block pool; zeroes msum1;
//       LAST BLOCK computes master2 (r2) inline ------------------------------
__global__ void __launch_bounds__(256) agg2_kernel(
    const float* __restrict__ b2, const void* __restrict__ batch,
    const float* __restrict__ mW2, const float* __restrict__ mb2, int N)
{
    __shared__ float zs[8][32];
    __shared__ int s_g0;
    __shared__ unsigned s_rank;
    int t = threadIdx.x;
    int wid = t >> 5;
    int lane = t & 31;
    int i = blockIdx.x * 8 + wid;
    int is64 = g_is64_batch;
    int gtid = blockIdx.x * 256 + t;
    if (gtid < GMAX * HDIM) g_msum1[gtid] = 0.f;   // tail-zero for next replay
    if (t == 0) {
        int n0 = blockIdx.x * 8;
        s_g0 = (n0 < N) ? (int)ld_idx(batch, n0, is64) : 0;
    }
    __syncthreads();
    int g0 = s_g0;

    float z = 0.f;
    int g = g0;
    bool active = (i < N);
    if (active) {
        int beg  = g_rowstart[i];
        int cntE = g_cnt_i[i];
        float acc = g_y2[(size_t)i * 32 + lane];
        int full = cntE & ~31;
        for (int k = 0; k < full; k += 32) {
            int myS = g_csr[beg + k + lane];
#pragma unroll 16
            for (int j = 0; j < 32; j++) {
                int s = __shfl_sync(0xffffffffu, myS, j);
                unsigned short raw = g_y2b[(size_t)s * 32 + lane];
                acc += __bfloat162float(*(__nv_bfloat16*)&raw);
            }
        }
        int rem = cntE - full;
        if (rem) {
            int myS = (lane < rem) ? g_csr[beg + full + lane] : 0;
            for (int j = 0; j < rem; j++) {
                int s = __shfl_sync(0xffffffffu, myS, j);
                unsigned short raw = g_y2b[(size_t)s * 32 + lane];
                acc += __bfloat162float(*(__nv_bfloat16*)&raw);
            }
        }
        z = g_dinv[i] * acc + b2[lane];
        g_z[(size_t)i * 32 + lane] = z;
        g = (int)ld_idx(batch, i, is64);
    }
    bool inblk = active && (g == g0);
    zs[wid][lane] = inblk ? z : 0.f;
    if (active && !inblk)
        atomicAdd(&g_msum2[g * KDIM + lane], z);
    __syncthreads();
    if (wid == 0) {
        float a = zs[0][lane];
#pragma unroll
        for (int w2 = 1; w2 < 8; w2++) a += zs[w2][lane];
        atomicAdd(&g_msum2[g0 * KDIM + lane], a);
    }
    // ---- grid-tail: last block computes master2 ----
    __threadfence();
    __syncthreads();
    if (t == 0) s_rank = atomicAdd(&g_tick2, 1);
    __syncthreads();
    if (s_rank == gridDim.x - 1) {
        __threadfence();
        if (t == 0) g_tick2 = 0;
        int j = t & 31;
        int gb = (t >> 5) * 8;       // 8 warps × 8 graphs
        for (int u = 0; u < 8; u++) {
            int gg = gb + u;
            float inv = 1.f / fmaxf(g_cnt[gg], 1.f);
            float a = mb2[j];
#pragma unroll 8
            for (int k = 0; k < KDIM; k++)
                a += (g_msum2[gg * KDIM + k] * inv) * mW2[k * KDIM + j];
            g_r2[gg * KDIM + j] = fmaxf(a, 0.f);
        }
    }
}

// ------- softmax (1 warp/row); tail-zeroes msum2 + cnt_i for next replay -----
__global__ void softmax_kernel(const void* __restrict__ batch,
                               float* __restrict__ out, int N) {
    int gtid = blockIdx.x * blockDim.x + threadIdx.x;
    if (gtid < GMAX * KDIM) g_msum2[gtid] = 0.f;
    if (gtid < N)           g_cnt_i[gtid] = 0;
    int i = gtid >> 5;
    int j = threadIdx.x & 31;
    if (i >= N) return;
    int g = (int)ld_idx(batch, i, g_is64_batch);
    float z = g_z[(size_t)i * 32 + j] + g_r2[g * 32 + j];
    float m = z;
#pragma unroll
    for (int o = 16; o > 0; o >>= 1) m = fmaxf(m, __shfl_xor_sync(0xffffffffu, m, o));
    float e = __expf(z - m);
    float s = e;
#pragma unroll
    for (int o = 16; o > 0; o >>= 1) s += __shfl_xor_sync(0xffffffffu, s, o);
    out[(size_t)i * 32 + j] = e / s;
}

// ---------------- launch ------------------------------------------------------
extern "C" void kernel_launch(void* const* d_in, const int* in_sizes, int n_in,
                              void* d_out, int out_size) {
    const float* X   = (const float*)d_in[0];
    const float* W1  = (const float*)d_in[1];
    const float* b1  = (const float*)d_in[2];
    const float* W2  = (const float*)d_in[3];
    const float* b2  = (const float*)d_in[4];
    const float* mW1 = (const float*)d_in[5];
    const float* mb1 = (const float*)d_in[6];
    const float* mW2 = (const float*)d_in[7];
    const float* mb2 = (const float*)d_in[8];
    const void*  ei  = d_in[9];
    const void*  bat = d_in[10];

    int N = in_sizes[0] / FDIM;
    long long E = in_sizes[9] / 2;
    float* out = (float*)d_out;

    int nScanBlocks = (N + 1023) / 1024;
    int edgeBlocks8 = (int)((E + 2047) / 2048);   // 8 edges/thread, 256 thr
    int aggBlocks   = (N + 7) / 8;                // 8 nodes (warps) per block

    static cudaStream_t s2 = nullptr;
    static cudaEvent_t evFork = nullptr, evJoin = nullptr;
    static int tried = 0;
    if (!tried) {
        tried = 1;
        if (cudaStreamCreateWithFlags(&s2, cudaStreamNonBlocking) != cudaSuccess) s2 = nullptr;
        if (s2) {
            if (cudaEventCreateWithFlags(&evFork, cudaEventDisableTiming) != cudaSuccess ||
                cudaEventCreateWithFlags(&evJoin, cudaEventDisableTiming) != cudaSuccess) {
                s2 = nullptr;
            }
        }
    }

    if (s2) {
        cudaEventRecord(evFork, 0);
        cudaStreamWaitEvent(s2, evFork, 0);
        detect_batch_kernel<<<1, 32, 0, s2>>>(bat, N);
        cnt_kernel<<<1, GMAX + 1, 0, s2>>>(bat, N);
        gemm1_kernel<<<(N + 63) / 64, 128, 0, s2>>>(X, W1, N);
        cudaEventRecord(evJoin, s2);
    }

    hist_kernel<<<edgeBlocks8, 256>>>(ei, E, N);
    scan1_kernel<<<nScanBlocks, 1024>>>(N);
    scan3_kernel<<<(N + 255) / 256, 256>>>(N, nScanBlocks);
    fill_kernel<<<edgeBlocks8, 256>>>(ei, E, N);

    if (s2) {
        cudaStreamWaitEvent(0, evJoin, 0);
    } else {
        detect_batch_kernel<<<1, 32>>>(bat, N);
        cnt_kernel<<<1, GMAX + 1>>>(bat, N);
        gemm1_kernel<<<(N + 63) / 64, 128>>>(X, W1, N);
    }

    agg1_kernel<<<aggBlocks, 256>>>(b1, bat, mW1, mb1, N);
    gemm2_kernel<<<(N + 127) / 128, 128>>>(bat, W2, N);
    agg2_kernel<<<aggBlocks, 256>>>(b2, bat, mW2, mb2, N);
    softmax_kernel<<<(N * 32 + 255) / 256, 256>>>(bat, out, N);
}

// round 14
// speedup vs baseline: 1.3408x; 1.3408x over previous
#include <cuda_runtime.h>
#include <cuda_bf16.h>
#include <math.h>

#define NMAX  50176
#define EMAX  1664000
#define GMAX  64
#define FDIM  128
#define HDIM  128
#define KDIM  32

typedef unsigned long long ull;

// ---------------- scratch (static device globals; no allocation) -------------
// INVARIANT: g_cnt_i, g_msum1, g_msum2 are zero at kernel_launch entry.
// (zero-initialized at module load; re-zeroed at the tail of each launch)
__device__ float g_dinv[NMAX];
__device__ uint2 g_y1b [NMAX * 32];     // bf16(xw = X@W1), 256B/row
__device__ uint2 g_hb  [NMAX * 32];     // bf16(h), 256B/row
__device__ float g_y2  [NMAX * KDIM];   // fp32 y2 (self-loop term)
__device__ unsigned short g_y2b[NMAX * KDIM];  // bf16 copy of y2
__device__ float g_z   [NMAX * KDIM];
__device__ float g_msum1[GMAX * HDIM];
__device__ float g_r1  [GMAX * HDIM];
__device__ float g_msum2[GMAX * KDIM];
__device__ float g_r2  [GMAX * KDIM];
__device__ float g_cnt [GMAX];
__device__ int   g_cnt_i[NMAX];
__device__ int   g_rowstart[NMAX];
__device__ int   g_cursor[NMAX];
__device__ int   g_bsums[64];
__device__ int   g_csr  [EMAX];
__device__ int   g_is64_batch;

__device__ __forceinline__ long long ld_idx(const void* p, long long pos, int is64) {
    if (is64) return ((const long long*)p)[pos];
    return (long long)((const int*)p)[pos];
}

__device__ __forceinline__ void fma2(ull& d, ull a, ull b) {
    asm("fma.rn.f32x2 %0, %1, %2, %0;" : "+l"(d) : "l"(a), "l"(b));
}
__device__ __forceinline__ ull pack2(float x, float y) {
    ull r; asm("mov.b64 %0, {%1, %2};" : "=l"(r) : "f"(x), "f"(y)); return r;
}
__device__ __forceinline__ void unpack2(ull v, float& x, float& y) {
    asm("mov.b64 {%0, %1}, %2;" : "=f"(x), "=f"(y) : "l"(v));
}
__device__ __forceinline__ uint2 pack_bf16x4(float a, float b, float c, float d) {
    __nv_bfloat162 lo = __floats2bfloat162_rn(a, b);
    __nv_bfloat162 hi = __floats2bfloat162_rn(c, d);
    uint2 o;
    o.x = *(unsigned*)&lo;
    o.y = *(unsigned*)&hi;
    return o;
}
__device__ __forceinline__ void unpack_bf16x4(uint2 v, float4& o) {
    float2 a = __bfloat1622float2(*(__nv_bfloat162*)&v.x);
    float2 b = __bfloat1622float2(*(__nv_bfloat162*)&v.y);
    o.x = a.x; o.y = a.y; o.z = b.x; o.w = b.y;
}

// In-block ei dtype detection: warp 0 samples 64 words, ballots, broadcasts.
__device__ __forceinline__ int detect_ei_block(const void* ei, long long E, int N,
                                               int* s_flag) {
    int t = threadIdx.x;
    if (t < 32) {
        const ull* p = (const ull*)ei;
        bool ok = true;
#pragma unroll
        for (int u = 0; u < 2; u++) {
            int i = t * 2 + u;
            long long w = (long long)i * (E - 1) / 63;
            if (p[w] >= (ull)N) ok = false;
        }
        unsigned all1 = __all_sync(0xffffffffu, ok);
        if (t == 0) *s_flag = (int)(all1 != 0);
    }
    __syncthreads();
    return *s_flag;
}

// side-stream: batch dtype (consumed by cnt/agg1/gemm2/agg2/softmax)
__global__ void detect_batch_kernel(const void* batch, int N) {
    int lane = threadIdx.x;
    const ull* q = (const ull*)batch;
    bool ok2 = true;
#pragma unroll
    for (int u = 0; u < 2; u++) {
        int i = lane * 2 + u;
        long long w = (long long)(N / 2) - 1 - i;
        if (w >= 0 && q[w] >= (ull)GMAX) ok2 = false;
    }
    unsigned all2 = __all_sync(0xffffffffu, ok2);
    if (lane == 0) g_is64_batch = (int)(all2 != 0);
}

// ------- per-graph node counts via binary search over sorted batch -----------
__global__ void cnt_kernel(const void* __restrict__ batch, int N) {
    int g = threadIdx.x;
    if (g > GMAX) return;
    __shared__ int start[GMAX + 1];
    int is64 = g_is64_batch;
    int lo = 0, hi = N;
    while (lo < hi) {
        int mid = (lo + hi) >> 1;
        int v = (int)ld_idx(batch, mid, is64);
        if (v < g) lo = mid + 1; else hi = mid;
    }
    start[g] = lo;
    __syncthreads();
    if (g < GMAX) g_cnt[g] = (float)(start[g + 1] - start[g]);
}

// ------------- degree histogram, 4 edges/thread; inline dtype detect ---------
__global__ void hist_kernel(const void* __restrict__ ei, long long E, int N) {
    __shared__ int s_flag;
    int is64 = detect_ei_block(ei, E, N, &s_flag);
    long long base = ((long long)blockIdx.x * blockDim.x + threadIdx.x) * 4;
    int d[4]; bool v[4];
#pragma unroll
    for (int u = 0; u < 4; u++) {
        long long e = base + u;
        v[u] = e < E;
        d[u] = v[u] ? (int)ld_idx(ei, E + e, is64) : 0;
    }
#pragma unroll
    for (int u = 0; u < 4; u++)
        if (v[u]) atomicAdd(&g_cnt_i[d[u]], 1);
}

// ------------- prefix-sum over node counts (2 kernels) ------------------------
__global__ void scan1_kernel(int N) {
    __shared__ int sm[1024];
    int t = threadIdx.x;
    int idx = blockIdx.x * 1024 + t;
    int val = (idx < N) ? g_cnt_i[idx] : 0;
    sm[t] = val;
    __syncthreads();
    for (int off = 1; off < 1024; off <<= 1) {
        int x = (t >= off) ? sm[t - off] : 0;
        __syncthreads();
        sm[t] += x;
        __syncthreads();
    }
    if (idx < N) g_rowstart[idx] = sm[t] - val;   // exclusive, block-local
    if (t == 1023) g_bsums[blockIdx.x] = sm[1023];
}
__global__ void scan3_kernel(int N, int nb) {
    __shared__ int pref[64];
    int t = threadIdx.x;
    if (t < 32) {
        int a = (t < nb) ? g_bsums[t] : 0;
        int b = (t + 32 < nb) ? g_bsums[t + 32] : 0;
        int sa = a, sb = b;
#pragma unroll
        for (int o = 1; o < 32; o <<= 1) {
            int va = __shfl_up_sync(0xffffffffu, sa, o);
            int vb = __shfl_up_sync(0xffffffffu, sb, o);
            if (t >= o) { sa += va; sb += vb; }
        }
        int totalA = __shfl_sync(0xffffffffu, sa, 31);
        pref[t]      = sa - a;
        pref[t + 32] = totalA + sb - b;
    }
    __syncthreads();
    int idx = blockIdx.x * blockDim.x + t;
    if (idx >= N) return;
    int v = g_rowstart[idx] + pref[idx >> 10];
    g_rowstart[idx] = v;
    g_cursor[idx]   = v;
    g_dinv[idx]     = rsqrtf((float)g_cnt_i[idx] + 1.0f);   // +1 self loop
}

// ------------- scatter-fill CSR, 4 edges/thread; inline dtype detect ----------
__global__ void fill_kernel(const void* __restrict__ ei, long long E, int N) {
    __shared__ int s_flag;
    int is64 = detect_ei_block(ei, E, N, &s_flag);
    long long base = ((long long)blockIdx.x * blockDim.x + threadIdx.x) * 4;
    int s[4], d[4]; bool v[4];
#pragma unroll
    for (int u = 0; u < 4; u++) {
        long long e = base + u;
        v[u] = e < E;
        s[u] = v[u] ? (int)ld_idx(ei, e, is64) : 0;
        d[u] = v[u] ? (int)ld_idx(ei, E + e, is64) : 0;
    }
#pragma unroll
    for (int u = 0; u < 4; u++) {
        if (v[u]) {
            int pos = atomicAdd(&g_cursor[d[u]], 1);
            g_csr[pos] = s[u];
        }
    }
}

// ------- GEMM1 (f32x2 FMAs): y1b = bf16(X @ W1)  (bf16-only output) ----------
__global__ void __launch_bounds__(128) gemm1_kernel(
    const float* __restrict__ X, const float* __restrict__ W, int N)
{
    __shared__ float As[16][64];
    __shared__ float Bs[16][128];
    int t  = threadIdx.x;
    int tx = t & 15;
    int ty = t >> 4;
    int rowBase = blockIdx.x * 64;

    ull acc2[8][4];
#pragma unroll
    for (int i = 0; i < 8; i++)
#pragma unroll
        for (int j = 0; j < 4; j++) acc2[i][j] = 0ULL;

    for (int k0 = 0; k0 < 128; k0 += 16) {
#pragma unroll
        for (int u = 0; u < 2; u++) {
            int idx = t * 8 + u * 4;
            int r = idx >> 4, c = idx & 15;
            int grow = rowBase + r;
            float4 v = make_float4(0.f, 0.f, 0.f, 0.f);
            if (grow < N) v = *(const float4*)(X + (size_t)grow * 128 + k0 + c);
            As[c + 0][r] = v.x; As[c + 1][r] = v.y;
            As[c + 2][r] = v.z; As[c + 3][r] = v.w;
        }
#pragma unroll
        for (int u = 0; u < 4; u++) {
            int idx = t * 16 + u * 4;
            int r = idx >> 7, c = idx & 127;
            *(float4*)&Bs[r][c] = *(const float4*)(W + (k0 + r) * 128 + c);
        }
        __syncthreads();
#pragma unroll
        for (int kk = 0; kk < 16; kk++) {
            float a[8];
            ull b2[4];
            *(float4*)&a[0] = *(float4*)&As[kk][ty * 8];
            *(float4*)&a[4] = *(float4*)&As[kk][ty * 8 + 4];
            *(ulonglong2*)&b2[0] = *(ulonglong2*)&Bs[kk][tx * 8];
            *(ulonglong2*)&b2[2] = *(ulonglong2*)&Bs[kk][tx * 8 + 4];
#pragma unroll
            for (int i = 0; i < 8; i++) {
                ull a2 = pack2(a[i], a[i]);
#pragma unroll
                for (int j = 0; j < 4; j++) fma2(acc2[i][j], a2, b2[j]);
            }
        }
        __syncthreads();
    }
#pragma unroll
    for (int i = 0; i < 8; i++) {
        int grow = rowBase + ty * 8 + i;
        if (grow < N) {
#pragma unroll
            for (int j2 = 0; j2 < 2; j2++) {
                float4 v;
                unpack2(acc2[i][j2 * 2 + 0], v.x, v.y);
                unpack2(acc2[i][j2 * 2 + 1], v.z, v.w);
                g_y1b[(size_t)grow * 32 + tx * 2 + j2] = pack_bf16x4(v.x, v.y, v.z, v.w);
            }
        }
    }
}

// ---- agg1: h = elu(dinv[i]*(dinv[i]*xw[i] + sum dinv[s]*xw[s]) + b1) --------
// Block-level pool reduction: 8 warps stage h in smem; warp 0 issues one
// red.v4 per block for the block's dominant graph; stragglers red directly.
__global__ void __launch_bounds__(256) agg1_kernel(
    const float* __restrict__ b1, const void* __restrict__ batch, int N)
{
    __shared__ float4 hs[8][32];
    __shared__ int s_g0;
    int t = threadIdx.x;
    int wid = t >> 5;
    int lane = t & 31;
    int i = blockIdx.x * 8 + wid;      // node index
    int is64 = g_is64_batch;
    if (t == 0) {
        int n0 = blockIdx.x * 8;
        s_g0 = (n0 < N) ? (int)ld_idx(batch, n0, is64) : 0;
    }
    __syncthreads();
    int g0 = s_g0;

    float4 h = make_float4(0.f, 0.f, 0.f, 0.f);
    int g = g0;
    bool active = (i < N);
    if (active) {
        int beg  = g_rowstart[i];
        int cntE = g_cnt_i[i];
        float dv = g_dinv[i];
        float4 self;
        unpack_bf16x4(g_y1b[(size_t)i * 32 + lane], self);
        float4 acc;
        acc.x = dv * self.x; acc.y = dv * self.y;
        acc.z = dv * self.z; acc.w = dv * self.w;
        int full = cntE & ~31;
        for (int k = 0; k < full; k += 32) {
            int   myS = g_csr[beg + k + lane];
            float myD = g_dinv[myS];
#pragma unroll 8
            for (int j = 0; j < 32; j++) {
                int   s = __shfl_sync(0xffffffffu, myS, j);
                float w = __shfl_sync(0xffffffffu, myD, j);
                float4 v;
                unpack_bf16x4(g_y1b[(size_t)s * 32 + lane], v);
                acc.x += w * v.x; acc.y += w * v.y;
                acc.z += w * v.z; acc.w += w * v.w;
            }
        }
        int rem = cntE - full;
        if (rem) {
            int   myS = (lane < rem) ? g_csr[beg + full + lane] : 0;
            float myD = (lane < rem) ? g_dinv[myS] : 0.f;
            for (int j = 0; j < rem; j++) {
                int   s = __shfl_sync(0xffffffffu, myS, j);
                float w = __shfl_sync(0xffffffffu, myD, j);
                float4 v;
                unpack_bf16x4(g_y1b[(size_t)s * 32 + lane], v);
                acc.x += w * v.x; acc.y += w * v.y;
                acc.z += w * v.z; acc.w += w * v.w;
            }
        }
        float4 bb = ((const float4*)b1)[lane];
        float vx = dv * acc.x + bb.x; h.x = vx > 0.f ? vx : expm1f(vx);
        float vy = dv * acc.y + bb.y; h.y = vy > 0.f ? vy : expm1f(vy);
        float vz = dv * acc.z + bb.z; h.z = vz > 0.f ? vz : expm1f(vz);
        float vw = dv * acc.w + bb.w; h.w = vw > 0.f ? vw : expm1f(vw);
        g_hb[(size_t)i * 32 + lane] = pack_bf16x4(h.x, h.y, h.z, h.w);
        g = (int)ld_idx(batch, i, is64);
    }
    // stage into smem if this warp matches the block graph, else direct red
    bool inblk = active && (g == g0);
    hs[wid][lane] = inblk ? h : make_float4(0.f, 0.f, 0.f, 0.f);
    if (active && !inblk) {
        float* ms = g_msum1 + g * HDIM + lane * 4;
        asm volatile("red.global.add.v4.f32 [%0], {%1, %2, %3, %4};"
                     :: "l"(ms), "f"(h.x), "f"(h.y), "f"(h.z), "f"(h.w) : "memory");
    }
    __syncthreads();
    if (wid == 0) {
        float4 a = hs[0][lane];
#pragma unroll
        for (int w2 = 1; w2 < 8; w2++) {
            float4 b = hs[w2][lane];
            a.x += b.x; a.y += b.y; a.z += b.z; a.w += b.w;
        }
        float* ms = g_msum1 + g0 * HDIM + lane * 4;
        asm volatile("red.global.add.v4.f32 [%0], {%1, %2, %3, %4};"
                     :: "l"(ms), "f"(a.x), "f"(a.y), "f"(a.z), "f"(a.w) : "memory");
    }
}

// ---------------- master1: r1 = relu(mean_pool(h) @ mW1 + mb1) ---------------
__global__ void master1_kernel(const float* __restrict__ mW1,
                               const float* __restrict__ mb1) {
    __shared__ float m[HDIM];
    int g = blockIdx.x, j = threadIdx.x;
    float c = fmaxf(g_cnt[g], 1.f);
    m[j] = g_msum1[g * HDIM + j] / c;
    __syncthreads();
    float a = mb1[j];
#pragma unroll 4
    for (int k = 0; k < HDIM; k++) a += m[k] * mW1[k * HDIM + j];
    g_r1[g * HDIM + j] = fmaxf(a, 0.f);
}

// --- GEMM2 (f32x2): y2 = dinv.*((bf16 h + r1[batch]) @ W2); bf16 copy y2b ----
__global__ void __launch_bounds__(128) gemm2_kernel(
    const void* __restrict__ batch, const float* __restrict__ W2, int N)
{
    __shared__ float Ws[128 * 32];
    int t = threadIdx.x;
#pragma unroll
    for (int u = 0; u < 8; u++) {
        int idx = u * 512 + t * 4;
        *(float4*)&Ws[idx] = *(const float4*)&W2[idx];
    }
    __syncthreads();
    int i = blockIdx.x * 128 + t;
    if (i >= N) return;
    int g = (int)ld_idx(batch, i, g_is64_batch);
    const uint2* hr = g_hb + (size_t)i * 32;
    const float* rr = g_r1 + g * 128;
    ull acc2[16];
#pragma unroll
    for (int j = 0; j < 16; j++) acc2[j] = 0ULL;
#pragma unroll 2
    for (int k0 = 0; k0 < 128; k0 += 4) {
        float4 xv;
        unpack_bf16x4(hr[k0 >> 2], xv);
        float4 rv = *(const float4*)(rr + k0);
        float xs[4] = {xv.x + rv.x, xv.y + rv.y, xv.z + rv.z, xv.w + rv.w};
#pragma unroll
        for (int kk = 0; kk < 4; kk++) {
            const ull* wrow = (const ull*)&Ws[(k0 + kk) * 32];
            ull x2 = pack2(xs[kk], xs[kk]);
#pragma unroll
            for (int j = 0; j < 16; j++) fma2(acc2[j], x2, wrow[j]);
        }
    }
    float dv = g_dinv[i];
#pragma unroll
    for (int j4 = 0; j4 < 8; j4++) {
        float4 v;
        unpack2(acc2[j4 * 2 + 0], v.x, v.y);
        unpack2(acc2[j4 * 2 + 1], v.z, v.w);
        v.x *= dv; v.y *= dv; v.z *= dv; v.w *= dv;
        *(float4*)(g_y2 + (size_t)i * 32 + j4 * 4) = v;
        __nv_bfloat162 lo = __floats2bfloat162_rn(v.x, v.y);
        __nv_bfloat162 hi = __floats2bfloat162_rn(v.z, v.w);
        unsigned* dstb = (unsigned*)(g_y2b + (size_t)i * 32 + j4 * 4);
        dstb[0] = *(unsigned*)&lo;
        dstb[1] = *(unsigned*)&hi;
    }
}

// ----- agg2: Z = dinv*(self + sum) + b2; block-level pool; zeroes msum1 ------
__global__ void __launch_bounds__(256) agg2_kernel(
    const float* __restrict__ b2, const void* __restrict__ batch, int N)
{
    __shared__ float zs[8][32];
    __shared__ int s_g0;
    int t = threadIdx.x;
    int wid = t >> 5;
    int lane = t & 31;
    int i = blockIdx.x * 8 + wid;
    int is64 = g_is64_batch;
    int gtid = blockIdx.x * 256 + t;
    if (gtid < GMAX * HDIM) g_msum1[gtid] = 0.f;   // tail-zero for next replay
    if (t == 0) {
        int n0 = blockIdx.x * 8;
        s_g0 = (n0 < N) ? (int)ld_idx(batch, n0, is64) : 0;
    }
    __syncthreads();
    int g0 = s_g0;

    float z = 0.f;
    int g = g0;
    bool active = (i < N);
    if (active) {
        int beg  = g_rowstart[i];
        int cntE = g_cnt_i[i];
        float acc = g_y2[(size_t)i * 32 + lane];
        int full = cntE & ~31;
        for (int k = 0; k < full; k += 32) {
            int myS = g_csr[beg + k + lane];
#pragma unroll 8
            for (int j = 0; j < 32; j++) {
                int s = __shfl_sync(0xffffffffu, myS, j);
                unsigned short raw = g_y2b[(size_t)s * 32 + lane];
                acc += __bfloat162float(*(__nv_bfloat16*)&raw);
            }
        }
        int rem = cntE - full;
        if (rem) {
            int myS = (lane < rem) ? g_csr[beg + full + lane] : 0;
            for (int j = 0; j < rem; j++) {
                int s = __shfl_sync(0xffffffffu, myS, j);
                unsigned short raw = g_y2b[(size_t)s * 32 + lane];
                acc += __bfloat162float(*(__nv_bfloat16*)&raw);
            }
        }
        z = g_dinv[i] * acc + b2[lane];
        g_z[(size_t)i * 32 + lane] = z;
        g = (int)ld_idx(batch, i, is64);
    }
    bool inblk = active && (g == g0);
    zs[wid][lane] = inblk ? z : 0.f;
    if (active && !inblk)
        atomicAdd(&g_msum2[g * KDIM + lane], z);
    __syncthreads();
    if (wid == 0) {
        float a = zs[0][lane];
#pragma unroll
        for (int w2 = 1; w2 < 8; w2++) a += zs[w2][lane];
        atomicAdd(&g_msum2[g0 * KDIM + lane], a);
    }
}

// ---------------- master2: r2 = relu(mean_pool(Z) @ mW2 + mb2) ---------------
__global__ void master2_kernel(const float* __restrict__ mW2,
                               const float* __restrict__ mb2) {
    __shared__ float m[KDIM];
    int g = blockIdx.x, j = threadIdx.x;
    float c = fmaxf(g_cnt[g], 1.f);
    m[j] = g_msum2[g * KDIM + j] / c;
    __syncthreads();
    float a = mb2[j];
#pragma unroll
    for (int k = 0; k < KDIM; k++) a += m[k] * mW2[k * KDIM + j];
    g_r2[g * KDIM + j] = fmaxf(a, 0.f);
}

// ------- softmax (1 warp/row); tail-zeroes msum2 + cnt_i for next replay -----
__global__ void softmax_kernel(const void* __restrict__ batch,
                               float* __restrict__ out, int N) {
    int gtid = blockIdx.x * blockDim.x + threadIdx.x;
    if (gtid < GMAX * KDIM) g_msum2[gtid] = 0.f;
    if (gtid < N)           g_cnt_i[gtid] = 0;
    int i = gtid >> 5;
    int j = threadIdx.x & 31;
    if (i >= N) return;
    int g = (int)ld_idx(batch, i, g_is64_batch);
    float z = g_z[(size_t)i * 32 + j] + g_r2[g * 32 + j];
    float m = z;
#pragma unroll
    for (int o = 16; o > 0; o >>= 1) m = fmaxf(m, __shfl_xor_sync(0xffffffffu, m, o));
    float e = __expf(z - m);
    float s = e;
#pragma unroll
    for (int o = 16; o > 0; o >>= 1) s += __shfl_xor_sync(0xffffffffu, s, o);
    out[(size_t)i * 32 + j] = e / s;
}

// ---------------- launch ------------------------------------------------------
extern "C" void kernel_launch(void* const* d_in, const int* in_sizes, int n_in,
                              void* d_out, int out_size) {
    const float* X   = (const float*)d_in[0];
    const float* W1  = (const float*)d_in[1];
    const float* b1  = (const float*)d_in[2];
    const float* W2  = (const float*)d_in[3];
    const float* b2  = (const float*)d_in[4];
    const float* mW1 = (const float*)d_in[5];
    const float* mb1 = (const float*)d_in[6];
    const float* mW2 = (const float*)d_in[7];
    const float* mb2 = (const float*)d_in[8];
    const void*  ei  = d_in[9];
    const void*  bat = d_in[10];

    int N = in_sizes[0] / FDIM;
    long long E = in_sizes[9] / 2;
    float* out = (float*)d_out;

    int nScanBlocks = (N + 1023) / 1024;
    int edgeBlocks4 = (int)((E + 1023) / 1024);
    int aggBlocks   = (N + 7) / 8;      // 8 nodes (warps) per block

    static cudaStream_t s2 = nullptr;
    static cudaEvent_t evFork = nullptr, evJoin = nullptr, evJoin2 = nullptr;
    static int tried = 0;
    if (!tried) {
        tried = 1;
        if (cudaStreamCreateWithFlags(&s2, cudaStreamNonBlocking) != cudaSuccess) s2 = nullptr;
        if (s2) {
            if (cudaEventCreateWithFlags(&evFork, cudaEventDisableTiming) != cudaSuccess ||
                cudaEventCreateWithFlags(&evJoin, cudaEventDisableTiming) != cudaSuccess ||
                cudaEventCreateWithFlags(&evJoin2, cudaEventDisableTiming) != cudaSuccess) {
                s2 = nullptr;
            }
        }
    }

    if (s2) {
        cudaEventRecord(evFork, 0);
        cudaStreamWaitEvent(s2, evFork, 0);
        detect_batch_kernel<<<1, 32, 0, s2>>>(bat, N);
        gemm1_kernel<<<(N + 63) / 64, 128, 0, s2>>>(X, W1, N);
        cudaEventRecord(evJoin, s2);
        cnt_kernel<<<1, GMAX + 1, 0, s2>>>(bat, N);   // overlaps agg1 on main
        cudaEventRecord(evJoin2, s2);
    }

    hist_kernel<<<edgeBlocks4, 256>>>(ei, E, N);
    scan1_kernel<<<nScanBlocks, 1024>>>(N);
    scan3_kernel<<<(N + 255) / 256, 256>>>(N, nScanBlocks);
    fill_kernel<<<edgeBlocks4, 256>>>(ei, E, N);

    if (s2) {
        cudaStreamWaitEvent(0, evJoin, 0);
    } else {
        detect_batch_kernel<<<1, 32>>>(bat, N);
        gemm1_kernel<<<(N + 63) / 64, 128>>>(X, W1, N);
        cnt_kernel<<<1, GMAX + 1>>>(bat, N);
    }

    agg1_kernel<<<aggBlocks, 256>>>(b1, bat, N);
    if (s2) cudaStreamWaitEvent(0, evJoin2, 0);
    master1_kernel<<<GMAX, HDIM>>>(mW1, mb1);
    gemm2_kernel<<<(N + 127) / 128, 128>>>(bat, W2, N);
    agg2_kernel<<<aggBlocks, 256>>>(b2, bat, N);
    master2_kernel<<<GMAX, KDIM>>>(mW2, mb2);
    softmax_kernel<<<(N * 32 + 255) / 256, 256>>>(bat, out, N);
}